// round 10
// baseline (speedup 1.0000x reference)
#include <cuda_runtime.h>

// SpatialAwareFocalLoss — GB300 sm_103a, round 10.
// R8 shape (grid=128: 2 CTAs/seq × 4 classes, 1024 thr) with bins fused into
// ONE packed u64 per line: {cnt:12 | tsum:14 | sig*2^25:38}. Halves the
// shared-atomic and window-read serial work. Packed-word global finish kept.

static constexpr int S    = 1024;   // SEQ_LEN
static constexpr int NBIN = 262;    // bin idx = line + 2, lines 0..255

static constexpr int           SIG_BITS = 38;
static constexpr unsigned long long SIG_MASK = (1ULL << SIG_BITS) - 1ULL;
static constexpr int           TS_SHIFT = 38;   // tsum at [51:38]
static constexpr int           CN_SHIFT = 52;   // cnt  at [63:52]
static constexpr float         SIG_SCALE   = 33554432.0f;       // 2^25
static constexpr float         SIG_INV     = 1.0f / 33554432.0f;

__device__ unsigned long long g_word = 0ULL;   // [63:48]=count, [47:0]=sum*2^32

__global__ __launch_bounds__(1024, 1)
void focal_kernel(const float* __restrict__ pred,
                  const float* __restrict__ target,
                  const int*   __restrict__ token_to_line,
                  float* __restrict__ out,
                  float inv_total, int nblocks)
{
    __shared__ unsigned long long s_bin[NBIN];  // packed {cnt|tsum|sigfix}
    __shared__ float s_red[32];

    const int bid  = blockIdx.x;
    const int b    = bid >> 1;        // sequence
    const int half = bid & 1;         // classes 0-3 or 4-7
    const int i    = threadIdx.x;
    const int lane = i & 31, warp = i >> 5;

    const long tok  = (long)b * S + i;
    const long base = tok * 8;

    // all independent loads issued up front (li gates the atomic phase)
    const int    li = __ldg(token_to_line + tok);
    const float4 p4 = __ldg((const float4*)(pred + base + half * 4));
    const float4 ta = __ldg((const float4*)(target + base));
    const float4 tb = __ldg((const float4*)(target + base + 4));

    if (i < NBIN) s_bin[i] = 0ULL;

    // full-class token target sum (small integer, exact) -> window gate
    const int tint = (int)(ta.x + ta.y + ta.z + ta.w + tb.x + tb.y + tb.z + tb.w);

    const float4 ts = half ? tb : ta;
    float p[4] = {p4.x, p4.y, p4.z, p4.w};
    float t[4] = {ts.x, ts.y, ts.z, ts.w};

    float sigsum = 0.0f, local = 0.0f;
    #pragma unroll
    for (int c = 0; c < 4; ++c) {
        const float x = p[c];
        const float e = __expf(-fabsf(x));
        const float a = 1.0f / (1.0f + e);        // sigmoid(|x|)
        const float g = e * a;                    // 1 - sigmoid(|x|)
        const float sig  = (x >= 0.0f) ? a : g;
        const float sig1 = (x >= 0.0f) ? g : a;   // 1 - sig
        sigsum += sig;
        const float pt  = (t[c] > 0.5f) ? sig : sig1;
        const float omp = (t[c] > 0.5f) ? sig1 : sig;   // 1 - pt
        const float bce = -__logf(pt);
        const float o2  = omp * omp;
        local += 0.01f * o2 * o2 * bce;           // ALPHA*(1-pt)^GAMMA*bce
    }

    // packed per-token contribution (fields can never cross-carry: cnt<=1024,
    // tsum<=8192, sigfix<=4096*2^25 < 2^38 for a whole 1024-token sequence)
    const unsigned long long sigfix =
        (unsigned long long)__float2uint_rn(sigsum * SIG_SCALE);
    const unsigned long long self =
        (1ULL << CN_SHIFT) | ((unsigned long long)tint << TS_SHIFT) | sigfix;

    __syncthreads();                              // barrier 1: bins zeroed

    atomicAdd(&s_bin[li + 2], self);
    __syncthreads();                              // barrier 2: bins complete

    // window lines [li-2, li+2] -> bins [li, li+4]; subtract self (no borrow:
    // every field of the window sum >= the corresponding field of self)
    unsigned long long w = 0ULL;
    #pragma unroll
    for (int k = 0; k < 5; ++k) w += s_bin[li + k];
    w -= self;

    const int cnt  = (int)(w >> CN_SHIFT);                // neighbors, no self
    const int ntgt = (int)((w >> TS_SHIFT) & 0x3FFFULL);  // exact integer gate
    if (cnt > 0 && ntgt > 0) {
        const float nsig = (float)(w & SIG_MASK) * SIG_INV;
        local += 0.03f * __fdividef(nsig, (float)cnt);
    }

    // block reduction
    #pragma unroll
    for (int o = 16; o > 0; o >>= 1)
        local += __shfl_xor_sync(0xffffffffu, local, o);
    if (lane == 0) s_red[warp] = local;
    __syncthreads();                              // barrier 3

    if (warp == 0) {
        float v = s_red[lane];
        #pragma unroll
        for (int o = 16; o > 0; o >>= 1)
            v += __shfl_xor_sync(0xffffffffu, v, o);

        if (lane == 0) {
            // v >= 0 always; fixed-point pack {count<<48 | sum*2^32}
            const unsigned long long fix =
                (unsigned long long)__double2ll_rn((double)v * 4294967296.0);
            const unsigned long long pack = (1ULL << 48) + fix;
            const unsigned long long old  = atomicAdd(&g_word, pack);

            if ((int)(old >> 48) == nblocks - 1) {      // last CTA
                const unsigned long long tot =
                    (old + pack) & ((1ULL << 48) - 1ULL);
                out[0] = (float)((double)tot * (1.0 / 4294967296.0)
                                 * (double)inv_total);
                atomicExch(&g_word, 0ULL);              // reset for next replay
            }
        }
    }
}

extern "C" void kernel_launch(void* const* d_in, const int* in_sizes, int n_in,
                              void* d_out, int out_size)
{
    const float* pred   = (const float*)d_in[0];
    const float* target = (const float*)d_in[1];
    const int*   lines  = (const int*)d_in[2];
    float* out = (float*)d_out;

    const int BS = in_sizes[2];
    const int B  = BS / S;
    const int nblocks = 2 * B;                    // 128 CTAs
    const float inv_total = 1.0f / ((float)BS * 8.0f);

    focal_kernel<<<nblocks, 1024>>>(pred, target, lines, out, inv_total, nblocks);
}

// round 11
// speedup vs baseline: 1.0372x; 1.0372x over previous
#include <cuda_runtime.h>

// SpatialAwareFocalLoss — GB300 sm_103a, round 11.
// R8 (empirical best: grid=128 = 2 CTAs/seq × 4 classes, 1024 thr, two-array
// line bins, packed-u64 single-atomic finish) re-benched with zero-risk tail
// trims: plain-store counter reset (no atomicExch round-trip).

static constexpr int S    = 1024;   // SEQ_LEN
static constexpr int NBIN = 262;    // bin idx = line + 2, lines 0..255

__device__ unsigned long long g_word = 0ULL;   // [63:48]=count, [47:0]=sum*2^32

__global__ __launch_bounds__(1024, 1)
void focal_kernel(const float* __restrict__ pred,
                  const float* __restrict__ target,
                  const int*   __restrict__ token_to_line,
                  float* __restrict__ out,
                  float inv_total, int nblocks)
{
    __shared__ int   s_bin_i[NBIN];  // cnt + (tsum<<16)
    __shared__ float s_bin_f[NBIN];  // this half's sigmoid sum per line
    __shared__ float s_red[32];

    const int bid  = blockIdx.x;
    const int b    = bid >> 1;        // sequence
    const int half = bid & 1;         // classes 0-3 or 4-7
    const int i    = threadIdx.x;
    const int lane = i & 31, warp = i >> 5;

    const long tok  = (long)b * S + i;
    const long base = tok * 8;

    // all independent loads issued up front (li gates the atomic phase)
    const int    li = __ldg(token_to_line + tok);
    const float4 p4 = __ldg((const float4*)(pred + base + half * 4));
    const float4 ta = __ldg((const float4*)(target + base));
    const float4 tb = __ldg((const float4*)(target + base + 4));

    if (i < NBIN) { s_bin_i[i] = 0; s_bin_f[i] = 0.0f; }

    // full-class token target sum (small integer, exact) -> window gate
    const int tint = (int)(ta.x + ta.y + ta.z + ta.w + tb.x + tb.y + tb.z + tb.w);

    const float4 ts = half ? tb : ta;
    float p[4] = {p4.x, p4.y, p4.z, p4.w};
    float t[4] = {ts.x, ts.y, ts.z, ts.w};

    float sigsum = 0.0f, local = 0.0f;
    #pragma unroll
    for (int c = 0; c < 4; ++c) {
        const float x = p[c];
        const float e = __expf(-fabsf(x));
        const float a = 1.0f / (1.0f + e);        // sigmoid(|x|)
        const float g = e * a;                    // 1 - sigmoid(|x|)
        const float sig  = (x >= 0.0f) ? a : g;
        const float sig1 = (x >= 0.0f) ? g : a;   // 1 - sig
        sigsum += sig;
        const float pt  = (t[c] > 0.5f) ? sig : sig1;
        const float omp = (t[c] > 0.5f) ? sig1 : sig;   // 1 - pt
        const float bce = -__logf(pt);
        const float o2  = omp * omp;
        local += 0.01f * o2 * o2 * bce;           // ALPHA*(1-pt)^GAMMA*bce
    }

    __syncthreads();                              // barrier 1: bins zeroed

    const int self_i = 1 + (tint << 16);
    atomicAdd(&s_bin_i[li + 2], self_i);
    atomicAdd(&s_bin_f[li + 2], sigsum);
    __syncthreads();                              // barrier 2: bins complete

    // window lines [li-2, li+2] -> bins [li, li+4]; exclude self
    int   ci   = -self_i;
    float nsig = -sigsum;
    #pragma unroll
    for (int k = 0; k < 5; ++k) {
        ci   += s_bin_i[li + k];
        nsig += s_bin_f[li + k];
    }
    const int cnt  = ci & 0xffff;                 // neighbors excluding self
    const int ntgt = ci >> 16;                    // exact integer gate

    if (cnt > 0 && ntgt > 0)
        local += 0.03f * __fdividef(nsig, (float)cnt);

    // block reduction
    #pragma unroll
    for (int o = 16; o > 0; o >>= 1)
        local += __shfl_xor_sync(0xffffffffu, local, o);
    if (lane == 0) s_red[warp] = local;
    __syncthreads();                              // barrier 3

    if (warp == 0) {
        float v = s_red[lane];
        #pragma unroll
        for (int o = 16; o > 0; o >>= 1)
            v += __shfl_xor_sync(0xffffffffu, v, o);

        if (lane == 0) {
            // v >= 0 always; fixed-point pack {count<<48 | sum*2^32}
            const unsigned long long fix =
                (unsigned long long)__double2ll_rn((double)v * 4294967296.0);
            const unsigned long long pack = (1ULL << 48) + fix;
            const unsigned long long old  = atomicAdd(&g_word, pack);

            if ((int)(old >> 48) == nblocks - 1) {      // last CTA
                const unsigned long long tot =
                    (old + pack) & ((1ULL << 48) - 1ULL);
                out[0] = (float)((double)tot *
                                 ((1.0 / 4294967296.0) * (double)inv_total));
                // plain store reset: same thread, same address ordering +
                // kernel-boundary coherence make this replay-safe
                *((volatile unsigned long long*)&g_word) = 0ULL;
            }
        }
    }
}

extern "C" void kernel_launch(void* const* d_in, const int* in_sizes, int n_in,
                              void* d_out, int out_size)
{
    const float* pred   = (const float*)d_in[0];
    const float* target = (const float*)d_in[1];
    const int*   lines  = (const int*)d_in[2];
    float* out = (float*)d_out;

    const int BS = in_sizes[2];
    const int B  = BS / S;
    const int nblocks = 2 * B;                    // 128 CTAs
    const float inv_total = 1.0f / ((float)BS * 8.0f);

    focal_kernel<<<nblocks, 1024>>>(pred, target, lines, out, inv_total, nblocks);
}